// round 3
// baseline (speedup 1.0000x reference)
#include <cuda_runtime.h>
#include <math.h>

#define DEPTH     512
#define NPAIR     255          // pairs 0..254 real; cols 510,511 have zero PE
#define VOCAB     198
#define NBLK      148          // row-chunk blocks (one per SM per wave)
#define THREADS   1024
#define HALF4     64           // float4s per depth-half (256 floats)
#define ROWSTEP   16           // rows advanced per loop iteration (1024/64)

// Phasor tables (.x = sin, .y = cos), indexed [slot*256 + j]
__device__ float2 g_Tblk[NBLK * 256];  // phasor(blk * RPB * w_j)
__device__ float2 g_Ttg [ROWSTEP * 256]; // phasor(tg * w_j), tg in [0,16)
__device__ float2 g_S16 [256];           // phasor(16 * w_j)

// ---------------------------------------------------------------------------
// Init: 512 threads. part 0 fills Tblk via f32 recurrence from fp64 seed;
// part 1 fills Ttg + S16. j = tid & 255.
// ---------------------------------------------------------------------------
__global__ void init_tables_kernel(int RPB)
{
    const int tid  = blockIdx.x * blockDim.x + threadIdx.x;
    if (tid >= 512) return;
    const int j    = tid & 255;
    const int part = tid >> 8;
    const double C = -9.210340371976184 / 256.0;   // -ln(10000)/256

    if (j >= NPAIR) {
        // pair 255: PE contribution must be zero
        if (part == 0) {
            for (int b = 0; b < NBLK; ++b) g_Tblk[b * 256 + j] = make_float2(0.f, 1.f);
        } else {
            for (int tg = 0; tg < ROWSTEP; ++tg) g_Ttg[tg * 256 + j] = make_float2(0.f, 0.f);
            g_S16[j] = make_float2(0.f, 1.f);       // identity rotation
        }
        return;
    }

    const double w = exp((double)j * C);

    if (part == 0) {
        double sa, ca;
        sincos((double)RPB * w, &sa, &ca);
        const float sx = (float)sa, cx = (float)ca;
        float s = 0.f, c = 1.f;
        for (int b = 0; b < NBLK; ++b) {
            g_Tblk[b * 256 + j] = make_float2(s, c);
            float ns = fmaf(s, cx,  c * sx);
            float nc = fmaf(c, cx, -s * sx);
            s = ns; c = nc;
        }
    } else {
        double sw, cw;
        sincos(w, &sw, &cw);
        const float sx = (float)sw, cx = (float)cw;
        float s = 0.f, c = 1.f;
        for (int tg = 0; tg < ROWSTEP; ++tg) {
            g_Ttg[tg * 256 + j] = make_float2(s, c);
            float ns = fmaf(s, cx,  c * sx);
            float nc = fmaf(c, cx, -s * sx);
            s = ns; c = nc;
        }
        double s16, c16;
        sincos(16.0 * w, &s16, &c16);
        g_S16[j] = make_float2((float)s16, (float)c16);
    }
}

// ---------------------------------------------------------------------------
// Main: grid (148, 2). blockIdx.x = row chunk, blockIdx.y = depth half.
// Wordlist half-slice (203 KB) staged in SMEM; gathers become LDS.128.
// ---------------------------------------------------------------------------
__global__ __launch_bounds__(THREADS, 1)
void emb_pe_kernel(const int* __restrict__ idx,
                   const float4* __restrict__ wl4,   // [VOCAB][128] float4
                   float4* __restrict__ out4,        // [L][128] float4
                   int L, int RPB)
{
    extern __shared__ char smem[];
    float4* sh_wl  = (float4*)smem;                          // [VOCAB][64]
    int*    sh_idx = (int*)(smem + VOCAB * HALF4 * 16);      // [RPB]

    const int blk  = blockIdx.x;
    const int h    = blockIdx.y;
    const int tid  = threadIdx.x;
    const int row0 = blk * RPB;
    if (row0 >= L) return;
    const int nrows = min(RPB, L - row0);

    // stage wordlist half-slice
    #pragma unroll 4
    for (int i = tid; i < VOCAB * HALF4; i += THREADS) {
        int vr = i >> 6, c = i & 63;
        sh_wl[i] = __ldg(&wl4[vr * (DEPTH / 4) + h * HALF4 + c]);
    }
    // stage idx tile
    for (int i = tid; i < nrows; i += THREADS)
        sh_idx[i] = idx[row0 + i];
    __syncthreads();

    const int tg = tid >> 6;          // row within 16-row group
    const int c  = tid & 63;          // float4 column within half
    const int j0 = h * 128 + 2 * c;
    const int j1 = j0 + 1;

    // base phasor = Tblk[blk] (x) Ttg[tg]
    float2 A0 = g_Tblk[blk * 256 + j0], B0 = g_Ttg[tg * 256 + j0], S0 = g_S16[j0];
    float2 A1 = g_Tblk[blk * 256 + j1], B1 = g_Ttg[tg * 256 + j1], S1 = g_S16[j1];

    float s0 = fmaf(A0.x, B0.y,  A0.y * B0.x);
    float c0 = fmaf(A0.y, B0.y, -A0.x * B0.x);
    float s1 = fmaf(A1.x, B1.y,  A1.y * B1.x);
    float c1 = fmaf(A1.y, B1.y, -A1.x * B1.x);

    float4* outp = out4 + (size_t)(row0 + tg) * (DEPTH / 4) + h * HALF4 + c;

    #pragma unroll 4
    for (int r = tg; r < nrows; r += ROWSTEP) {
        int token = sh_idx[r];
        float4 e = sh_wl[token * HALF4 + c];
        float4 o;
        o.x = e.x + s0;
        o.y = e.y + c0;
        o.z = e.z + s1;
        o.w = e.w + c1;
        __stcs(outp, o);
        outp += ROWSTEP * (DEPTH / 4);

        float ns0 = fmaf(s0, S0.y,  c0 * S0.x);
        float nc0 = fmaf(c0, S0.y, -s0 * S0.x);
        float ns1 = fmaf(s1, S1.y,  c1 * S1.x);
        float nc1 = fmaf(c1, S1.y, -s1 * S1.x);
        s0 = ns0; c0 = nc0; s1 = ns1; c1 = nc1;
    }
}

extern "C" void kernel_launch(void* const* d_in, const int* in_sizes, int n_in,
                              void* d_out, int out_size)
{
    const int*   idx = (const int*)d_in[0];
    const float* wl  = (const float*)d_in[1];
    float*       out = (float*)d_out;

    int L   = in_sizes[0];
    int RPB = (L + NBLK - 1) / NBLK;

    size_t smem_bytes = (size_t)VOCAB * HALF4 * 16 + (size_t)RPB * 4;
    cudaFuncSetAttribute(emb_pe_kernel,
                         cudaFuncAttributeMaxDynamicSharedMemorySize,
                         (int)smem_bytes);

    init_tables_kernel<<<16, 32>>>(RPB);

    dim3 grid(NBLK, 2);
    emb_pe_kernel<<<grid, THREADS, smem_bytes>>>(idx, (const float4*)wl,
                                                 (float4*)out, L, RPB);
}

// round 4
// speedup vs baseline: 1.1244x; 1.1244x over previous
#include <cuda_runtime.h>
#include <math.h>

#define DEPTH    512
#define NPAIR    255        // pairs 0..254 real; cols 510,511 zero PE
#define ROWS     32         // rows per block
#define THREADS  128        // 2 row-groups x 64 float4 columns (one depth half)
#define HALF4    64         // float4s per half (256 floats)
#define QH_N     64
#define QL_N     64

// Phasor tables (.x = sin, .y = cos), index [slot*256 + j]
__device__ float2 g_T1  [QH_N * 256];  // phasor(qh * 2048 * w_j)
__device__ float2 g_T2  [QL_N * 256];  // phasor(ql * 32   * w_j)
__device__ float2 g_Trow[2 * 256];     // phasor(tg * w_j), tg in {0,1}
__device__ float2 g_S2  [256];         // phasor(2 * w_j)   (row step)

__device__ __forceinline__ float2 cmul(float2 a, float2 b)
{   // (sin,cos) angle addition
    return make_float2(fmaf(a.x, b.y,  a.y * b.x),
                       fmaf(a.y, b.y, -a.x * b.x));
}

// ---------------------------------------------------------------------------
// Init: 512 threads; j = tid & 255. part0 fills T1, part1 fills T2/Trow/S2.
// 64-step f32 recurrences seeded by fp64 sincos (error ~1e-6, negligible).
// ---------------------------------------------------------------------------
__global__ void init_tables_kernel()
{
    const int tid  = blockIdx.x * blockDim.x + threadIdx.x;
    if (tid >= 512) return;
    const int j    = tid & 255;
    const int part = tid >> 8;
    const double C = -9.210340371976184 / 256.0;   // -ln(10000)/256

    if (j >= NPAIR) {
        if (part == 0) {
            for (int q = 0; q < QH_N; ++q) g_T1[q * 256 + j] = make_float2(0.f, 1.f);
        } else {
            for (int q = 0; q < QL_N; ++q) g_T2[q * 256 + j] = make_float2(0.f, 1.f);
            g_Trow[j]       = make_float2(0.f, 0.f);   // zeroes the pair
            g_Trow[256 + j] = make_float2(0.f, 0.f);
            g_S2[j]         = make_float2(0.f, 1.f);   // identity step
        }
        return;
    }

    const double w = exp((double)j * C);

    if (part == 0) {
        double sa, ca; sincos(2048.0 * w, &sa, &ca);
        float2 step = make_float2((float)sa, (float)ca);
        float2 v = make_float2(0.f, 1.f);
        for (int q = 0; q < QH_N; ++q) {
            g_T1[q * 256 + j] = v;
            v = cmul(v, step);
        }
    } else {
        double sa, ca; sincos(32.0 * w, &sa, &ca);
        float2 step = make_float2((float)sa, (float)ca);
        float2 v = make_float2(0.f, 1.f);
        for (int q = 0; q < QL_N; ++q) {
            g_T2[q * 256 + j] = v;
            v = cmul(v, step);
        }
        double sw, cw;  sincos(w,       &sw,  &cw);
        double s2, c2;  sincos(2.0 * w, &s2,  &c2);
        g_Trow[j]       = make_float2(0.f, 1.f);
        g_Trow[256 + j] = make_float2((float)sw, (float)cw);
        g_S2[j]         = make_float2((float)s2, (float)c2);
    }
}

// ---------------------------------------------------------------------------
// Main: 1-D grid, halves-major: bid = h * nchunks + chunk.
// Block handles 32 rows x one 256-col depth half; per-SM wordlist
// footprint 203 KB -> L1-resident gathers.
// ---------------------------------------------------------------------------
__global__ __launch_bounds__(THREADS)
void emb_pe_kernel(const int* __restrict__ idx,
                   const float4* __restrict__ wl4,   // [VOCAB][128] float4
                   float4* __restrict__ out4,        // [L][128] float4
                   int L, int nchunks)
{
    __shared__ int sh_idx[ROWS];

    const int bid   = blockIdx.x;
    const int h     = (bid >= nchunks) ? 1 : 0;
    const int chunk = bid - h * nchunks;
    const int row0  = chunk * ROWS;
    const int nrows = min(ROWS, L - row0);
    const int tid   = threadIdx.x;

    if (tid < nrows) sh_idx[tid] = idx[row0 + tid];
    __syncthreads();

    const int tg = tid >> 6;          // 0 or 1: row parity within chunk
    const int c  = tid & 63;          // float4 column within half
    const int j0 = h * 128 + 2 * c;   // pair ids for this float4
    const int j1 = j0 + 1;
    const int qh = chunk >> 6;
    const int ql = chunk & 63;

    // base phasor = T1[qh] * T2[ql] * Trow[tg]
    float2 P0 = cmul(cmul(g_T1[(qh << 8) + j0], g_T2[(ql << 8) + j0]),
                     g_Trow[(tg << 8) + j0]);
    float2 P1 = cmul(cmul(g_T1[(qh << 8) + j1], g_T2[(ql << 8) + j1]),
                     g_Trow[(tg << 8) + j1]);
    const float2 S0 = g_S2[j0];
    const float2 S1 = g_S2[j1];

    float s0 = P0.x, c0 = P0.y, s1 = P1.x, c1 = P1.y;

    const int colbase = h * HALF4 + c;
    float4* outp = out4 + (size_t)(row0 + tg) * (DEPTH / 4) + colbase;

    #pragma unroll 8
    for (int r = tg; r < nrows; r += 2) {
        int token = sh_idx[r];
        float4 e = __ldg(&wl4[token * (DEPTH / 4) + colbase]);
        float4 o;
        o.x = e.x + s0;
        o.y = e.y + c0;
        o.z = e.z + s1;
        o.w = e.w + c1;
        __stcs(outp, o);
        outp += 2 * (DEPTH / 4);

        float ns0 = fmaf(s0, S0.y,  c0 * S0.x);
        float nc0 = fmaf(c0, S0.y, -s0 * S0.x);
        float ns1 = fmaf(s1, S1.y,  c1 * S1.x);
        float nc1 = fmaf(c1, S1.y, -s1 * S1.x);
        s0 = ns0; c0 = nc0; s1 = ns1; c1 = nc1;
    }
}

extern "C" void kernel_launch(void* const* d_in, const int* in_sizes, int n_in,
                              void* d_out, int out_size)
{
    const int*   idx = (const int*)d_in[0];
    const float* wl  = (const float*)d_in[1];
    float*       out = (float*)d_out;

    int L       = in_sizes[0];
    int nchunks = (L + ROWS - 1) / ROWS;

    init_tables_kernel<<<4, 128>>>();

    emb_pe_kernel<<<2 * nchunks, THREADS>>>(idx, (const float4*)wl,
                                            (float4*)out, L, nchunks);
}